// round 10
// baseline (speedup 1.0000x reference)
#include <cuda_runtime.h>
#include <cuda_fp16.h>
#include <math.h>

// ---------------- problem constants ----------------
#define NOPEN 64
#define NNIN  16
#define MAXN  65536
#define MAXE  4000000           // capacity for 2*nE incident entries
#define DTH   0.025f            // dt*H = (1/4)*0.1
#define SCAN_B 256

// ---------------- device scratch ----------------
__device__ float          g_x[(size_t)MAXN * NOPEN];   // node features (f32)
__device__ unsigned short g_p8[2][(size_t)MAXN * 32];  // ping-pong p (e4m3x2/lane)
__device__ float          g_d2[MAXN];                  // 1/deg
__device__ int            g_deg[MAXN];
__device__ int            g_cnt[MAXN];                 // incident count
__device__ int            g_off[MAXN];                 // CSR offsets
__device__ int            g_cur[MAXN];                 // fill cursors
__device__ unsigned       g_adj[MAXE];                 // (nbr<<16) | f16bits(+-w2)
__device__ int            g_bsum[256];
__device__ int            g_bpre[256];

// ---------------- fp8 helpers ----------------
static __device__ __forceinline__ __half2 fp8x2_to_half2(unsigned short u) {
    unsigned r;
    asm("cvt.rn.f16x2.e4m3x2 %0, %1;" : "=r"(r) : "h"(u));
    return *(__half2*)&r;
}
static __device__ __forceinline__ unsigned short f32x2_to_fp8x2(float lo, float hi) {
    unsigned short u;
    asm("cvt.rn.satfinite.e4m3x2.f32 %0, %1, %2;" : "=h"(u) : "f"(hi), "f"(lo));
    return u;
}

// ---------------- init / fused count ----------------
__global__ void init_kernel(int nN) {
    int i = blockIdx.x * blockDim.x + threadIdx.x;
    if (i < nN) { g_deg[i] = 1; g_cnt[i] = 0; }
}
__global__ void count_kernel(const int* __restrict__ iInd,
                             const int* __restrict__ jInd, int nE) {
    int e = blockIdx.x * blockDim.x + threadIdx.x;
    if (e >= nE) return;
    int I = iInd[e], J = jInd[e];
    atomicAdd(&g_deg[J], 1);
    atomicAdd(&g_cnt[I], 1);
    atomicAdd(&g_cnt[J], 1);
}
__global__ void d2_kernel(int nN) {
    int i = blockIdx.x * blockDim.x + threadIdx.x;
    if (i < nN) g_d2[i] = 1.0f / (float)g_deg[i];
}

// ---------------- 3-phase scan (coalesced) ----------------
__global__ void __launch_bounds__(SCAN_B)
scanA_kernel(int nPad4) {
    __shared__ int sSum[SCAN_B];
    int idx4 = blockIdx.x * SCAN_B + threadIdx.x;
    int4 v = (idx4 < nPad4) ? ((const int4*)g_cnt)[idx4] : make_int4(0, 0, 0, 0);
    sSum[threadIdx.x] = v.x + v.y + v.z + v.w;
    __syncthreads();
    for (int d = SCAN_B / 2; d; d >>= 1) {
        if (threadIdx.x < d) sSum[threadIdx.x] += sSum[threadIdx.x + d];
        __syncthreads();
    }
    if (threadIdx.x == 0) g_bsum[blockIdx.x] = sSum[0];
}
__global__ void __launch_bounds__(256)
scanB_kernel(int nBlocks) {
    __shared__ int sV[256];
    int t = threadIdx.x;
    sV[t] = (t < nBlocks) ? g_bsum[t] : 0;
    __syncthreads();
    for (int d = 1; d < 256; d <<= 1) {
        int v = (t >= d) ? sV[t - d] : 0;
        __syncthreads();
        sV[t] += v;
        __syncthreads();
    }
    if (t < nBlocks) g_bpre[t] = sV[t] - g_bsum[t];
}
__global__ void __launch_bounds__(SCAN_B)
scanC_kernel(int nPad4) {
    __shared__ int sV[SCAN_B];
    int idx4 = blockIdx.x * SCAN_B + threadIdx.x;
    int4 v = (idx4 < nPad4) ? ((const int4*)g_cnt)[idx4] : make_int4(0, 0, 0, 0);
    int tsum = v.x + v.y + v.z + v.w;
    sV[threadIdx.x] = tsum;
    __syncthreads();
    for (int d = 1; d < SCAN_B; d <<= 1) {
        int u = (threadIdx.x >= d) ? sV[threadIdx.x - d] : 0;
        __syncthreads();
        sV[threadIdx.x] += u;
        __syncthreads();
    }
    int base = g_bpre[blockIdx.x] + sV[threadIdx.x] - tsum;
    if (idx4 < nPad4) {
        int4 o;
        o.x = base;
        o.y = base + v.x;
        o.z = base + v.x + v.y;
        o.w = base + v.x + v.y + v.z;
        ((int4*)g_off)[idx4] = o;
        ((int4*)g_cur)[idx4] = o;
    }
}

__global__ void fill_kernel(const int* __restrict__ iInd,
                            const int* __restrict__ jInd, int nE) {
    int e = blockIdx.x * blockDim.x + threadIdx.x;
    if (e >= nE) return;
    int I = iInd[e], J = jInd[e];
    float w2 = g_d2[I] * g_d2[J];
    unsigned short hb = __half_as_ushort(__float2half(w2));
    int pI = atomicAdd(&g_cur[I], 1);
    g_adj[pI] = ((unsigned)J << 16) | hb;              // +w2: use fmax(t,0)
    int pJ = atomicAdd(&g_cur[J], 1);
    g_adj[pJ] = ((unsigned)I << 16) | hb | 0x8000u;    // -w2: use fmin(t,0)
}

// ---------------- x0 = relu(K1Nopen @ xn) ----------------
__global__ void __launch_bounds__(256)
x0_kernel(const float* __restrict__ xn, const float* __restrict__ K1, int nN) {
    __shared__ float sK[NNIN * NOPEN];       // sK[c*64+o] = K1[o][c]
    __shared__ float sX[NNIN][256];
    for (int idx = threadIdx.x; idx < NOPEN * NNIN; idx += blockDim.x) {
        int o = idx >> 4, c = idx & 15;
        sK[c * NOPEN + o] = K1[idx];
    }
    int n0 = blockIdx.x * 256;
    for (int idx = threadIdx.x; idx < NNIN * 256; idx += blockDim.x) {
        int c = idx >> 8, nn = idx & 255;
        int n = n0 + nn;
        sX[c][nn] = (n < nN) ? xn[(size_t)c * nN + n] : 0.f;
    }
    __syncthreads();

    int n = n0 + threadIdx.x;
    if (n >= nN) return;
    float* dst = &g_x[(size_t)n * NOPEN];
#pragma unroll
    for (int half = 0; half < 2; half++) {
        float acc[32];
#pragma unroll
        for (int o = 0; o < 32; o++) acc[o] = 0.f;
#pragma unroll
        for (int c = 0; c < NNIN; c++) {
            float xc = sX[c][threadIdx.x];
#pragma unroll
            for (int o = 0; o < 32; o++)
                acc[o] += sK[c * NOPEN + half * 32 + o] * xc;
        }
#pragma unroll
        for (int o4 = 0; o4 < 8; o4++) {
            float4 r;
            r.x = fmaxf(acc[4 * o4 + 0], 0.f);
            r.y = fmaxf(acc[4 * o4 + 1], 0.f);
            r.z = fmaxf(acc[4 * o4 + 2], 0.f);
            r.w = fmaxf(acc[4 * o4 + 3], 0.f);
            ((float4*)dst)[half * 8 + o4] = r;
        }
    }
}

// ---------------- pre: p0 = fp8(KN1 @ x) (warp per node) ----------------
__global__ void __launch_bounds__(256)
pre_kernel(const float* __restrict__ KN1w, int nN) {
    __shared__ float sKp[64 * 66];           // sKp[k*66+o] = KN1[o][k]
    __shared__ float sRow[8][64];
    for (int idx = threadIdx.x; idx < 64 * 64; idx += blockDim.x) {
        int r = idx >> 6, c = idx & 63;
        sKp[c * 66 + r] = KN1w[idx];
    }
    __syncthreads();

    int lane = threadIdx.x & 31;
    int ws   = threadIdx.x >> 5;
    int n    = blockIdx.x * 8 + ws;
    if (n >= nN) return;
    int o0 = 2 * lane;

    float2 xv = *(const float2*)&g_x[(size_t)n * NOPEN + o0];
    sRow[ws][o0] = xv.x; sRow[ws][o0 + 1] = xv.y;
    __syncwarp();
    float p0 = 0.f, p1 = 0.f;
#pragma unroll 8
    for (int k = 0; k < 64; k++) {
        float xk = sRow[ws][k];
        float2 a = *(const float2*)&sKp[k * 66 + o0];
        p0 += a.x * xk;
        p1 += a.y * xk;
    }
    g_p8[0][(size_t)n * 32 + lane] = f32x2_to_fp8x2(p0, p1);
}

// ---------------- fused layer ----------------
__global__ void __launch_bounds__(256)
layer_kernel(const float* __restrict__ KN1w, const float* __restrict__ KC,
             float* __restrict__ out, int nN, int inbuf, int last) {
    __shared__ float sKy[64 * 66];           // sKy[k*66+o] = KN1[k][o]
    __shared__ float sKp[64 * 66];           // mid: KN1[o][k] ; last: KC[o][i]
    __shared__ float sRow[8][64];
    const float* P2 = last ? KC : KN1w;
    for (int idx = threadIdx.x; idx < 64 * 64; idx += blockDim.x) {
        int r = idx >> 6, c = idx & 63;
        sKy[r * 66 + c] = KN1w[idx];
        sKp[c * 66 + r] = P2[idx];
    }
    __syncthreads();

    const unsigned short* pin  = g_p8[inbuf];
    unsigned short*       pout = g_p8[inbuf ^ 1];

    int lane = threadIdx.x & 31;
    int ws   = threadIdx.x >> 5;
    int n    = blockIdx.x * 8 + ws;
    if (n >= nN) return;

    int beg = g_off[n];
    int cnt = g_cnt[n];
    __half2 psh = fp8x2_to_half2(pin[(size_t)n * 32 + lane]);
    const __half2 zero2 = __float2half2_rn(0.f);
    __half2 accA = zero2, accB = zero2;

    for (int t0 = 0; t0 < cnt; t0 += 32) {
        int idx = t0 + lane;
        unsigned v = (idx < cnt) ? __ldg(&g_adj[beg + idx]) : 0u;  // w=+0 -> 0
#pragma unroll
        for (int h = 0; h < 2; h++) {
            unsigned vv[16];
            unsigned short pbv[16];
#pragma unroll
            for (int c = 0; c < 16; c++)
                vv[c] = __shfl_sync(0xffffffffu, v, h * 16 + c);
#pragma unroll
            for (int c = 0; c < 16; c++)
                pbv[c] = __ldg(&pin[(size_t)(vv[c] >> 16) * 32 + lane]);
#pragma unroll
            for (int c = 0; c < 16; c++) {
                __half2 pb = fp8x2_to_half2(pbv[c]);
                __half2 t = __hsub2(psh, pb);
                unsigned short wb = (unsigned short)(vv[c] & 0x7fffu);
                __half2 w2h = __half2half2(__ushort_as_half(wb));
                __half2 d = (vv[c] & 0x8000u) ? __hmin2(t, zero2)
                                              : __hmax2(t, zero2);
                if (c & 1) accB = __hfma2(d, w2h, accB);
                else       accA = __hfma2(d, w2h, accA);
            }
        }
    }
    float2 sa = __half22float2(accA);
    float2 sb = __half22float2(accB);
    float sx = sa.x + sb.x, sy = sa.y + sb.y;

    // stage s, apply KN1^T
    int o0 = 2 * lane;
    sRow[ws][o0] = sx; sRow[ws][o0 + 1] = sy;
    __syncwarp();
    float y0 = 0.f, y1 = 0.f;
#pragma unroll 8
    for (int k = 0; k < 64; k++) {
        float sk = sRow[ws][k];
        float2 av = *(const float2*)&sKy[k * 66 + o0];
        y0 += av.x * sk;
        y1 += av.y * sk;
    }
    size_t off = (size_t)n * NOPEN + o0;
    float2 xv = *(const float2*)&g_x[off];
    xv.x -= DTH * y0;
    xv.y -= DTH * y1;

    __syncwarp();
    sRow[ws][o0] = xv.x; sRow[ws][o0 + 1] = xv.y;
    __syncwarp();
    float v0 = 0.f, v1 = 0.f;
#pragma unroll 8
    for (int k = 0; k < 64; k++) {
        float xk = sRow[ws][k];
        float2 av = *(const float2*)&sKp[k * 66 + o0];
        v0 += av.x * xk;
        v1 += av.y * xk;
    }

    if (!last) {
        *(float2*)&g_x[off] = xv;
        pout[(size_t)n * 32 + lane] = f32x2_to_fp8x2(v0, v1);
    } else {
        float m = fmaxf(v0, v1);
#pragma unroll
        for (int o = 16; o; o >>= 1)
            m = fmaxf(m, __shfl_xor_sync(0xffffffffu, m, o));
        float s = expf(v0 - m) + expf(v1 - m);
#pragma unroll
        for (int o = 16; o; o >>= 1)
            s += __shfl_xor_sync(0xffffffffu, s, o);
        float lse = m + logf(s);
        float2 r;
        r.x = v0 - lse;
        r.y = v1 - lse;
        *(float2*)&out[(size_t)n * NOPEN + o0] = r;
    }
}

// ---------------- launch ----------------
extern "C" void kernel_launch(void* const* d_in, const int* in_sizes, int n_in,
                              void* d_out, int out_size) {
    const float* xn   = (const float*)d_in[0];
    const int*   iInd = (const int*)d_in[1];
    const int*   jInd = (const int*)d_in[2];
    int base = 3;
    if (n_in >= 7 && in_sizes[3] == 1) base = 4;
    const float* K1  = (const float*)d_in[base];
    const float* KN1 = (const float*)d_in[base + 1];
    const float* KC  = (const float*)d_in[base + 2];

    int nN = in_sizes[0] / NNIN;
    int nE = in_sizes[1];

    int nodeBlocks = (nN + 7) / 8;
    int nb256 = (nN + 255) / 256;
    int eb256 = (nE + 255) / 256;
    int nPad4 = (nN + 3) / 4;
    int scanBlocks = (nPad4 + SCAN_B - 1) / SCAN_B;

    // CSR build + norm
    init_kernel<<<nb256, 256>>>(nN);
    count_kernel<<<eb256, 256>>>(iInd, jInd, nE);
    d2_kernel<<<nb256, 256>>>(nN);
    scanA_kernel<<<scanBlocks, SCAN_B>>>(nPad4);
    scanB_kernel<<<1, 256>>>(scanBlocks);
    scanC_kernel<<<scanBlocks, SCAN_B>>>(nPad4);
    fill_kernel<<<eb256, 256>>>(iInd, jInd, nE);

    // network
    x0_kernel<<<nb256, 256>>>(xn, K1, nN);
    pre_kernel<<<nodeBlocks, 256>>>(KN1, nN);
    for (int l = 0; l < 4; l++)
        layer_kernel<<<nodeBlocks, 256>>>(KN1, KC, (float*)d_out, nN, l & 1,
                                          l == 3 ? 1 : 0);
}

// round 11
// speedup vs baseline: 1.1202x; 1.1202x over previous
#include <cuda_runtime.h>
#include <cuda_fp16.h>
#include <math.h>

// ---------------- problem constants ----------------
#define NOPEN 64
#define NNIN  16
#define MAXN  65536
#define MAXE  4000000           // capacity for 2*nE incident entries
#define DTH   0.025f            // dt*H = (1/4)*0.1
#define SCAN_B 256

// ---------------- device scratch ----------------
__device__ float          g_x[(size_t)MAXN * NOPEN];   // node features (f32)
__device__ unsigned short g_p8[2][(size_t)MAXN * 32];  // ping-pong p (e4m3x2/lane)
__device__ float          g_d2[MAXN];                  // 1/deg
__device__ int            g_deg[MAXN];
__device__ int            g_cnt[MAXN];                 // incident count
__device__ int            g_off[MAXN];                 // CSR offsets
__device__ int            g_cur[MAXN];                 // fill cursors
__device__ unsigned       g_adj[MAXE];                 // (nbr<<16) | f16bits(+-w2)
__device__ int            g_bsum[256];
__device__ int            g_bpre[256];

// ---------------- fp8 helpers ----------------
static __device__ __forceinline__ unsigned short f32x2_to_fp8x2(float lo, float hi) {
    unsigned short u;
    asm("cvt.rn.satfinite.e4m3x2.f32 %0, %1, %2;" : "=h"(u) : "f"(hi), "f"(lo));
    return u;
}
// one u32 = 4 fp8 = 2 fp8x2 -> two half2
static __device__ __forceinline__ void fp8x4_to_2half2(unsigned u, __half2& a, __half2& b) {
    unsigned r0, r1;
    asm("{\n\t"
        ".reg .b16 l, h;\n\t"
        "mov.b32 {l, h}, %2;\n\t"
        "cvt.rn.f16x2.e4m3x2 %0, l;\n\t"
        "cvt.rn.f16x2.e4m3x2 %1, h;\n\t"
        "}" : "=r"(r0), "=r"(r1) : "r"(u));
    a = *(__half2*)&r0;
    b = *(__half2*)&r1;
}

// ---------------- init / fused count ----------------
__global__ void init_kernel(int nN) {
    int i = blockIdx.x * blockDim.x + threadIdx.x;
    if (i < nN) { g_deg[i] = 1; g_cnt[i] = 0; }
}
__global__ void count_kernel(const int* __restrict__ iInd,
                             const int* __restrict__ jInd, int nE) {
    int e = blockIdx.x * blockDim.x + threadIdx.x;
    if (e >= nE) return;
    int I = iInd[e], J = jInd[e];
    atomicAdd(&g_deg[J], 1);
    atomicAdd(&g_cnt[I], 1);
    atomicAdd(&g_cnt[J], 1);
}
__global__ void d2_kernel(int nN) {
    int i = blockIdx.x * blockDim.x + threadIdx.x;
    if (i < nN) g_d2[i] = 1.0f / (float)g_deg[i];
}

// ---------------- 3-phase scan (coalesced) ----------------
__global__ void __launch_bounds__(SCAN_B)
scanA_kernel(int nPad4) {
    __shared__ int sSum[SCAN_B];
    int idx4 = blockIdx.x * SCAN_B + threadIdx.x;
    int4 v = (idx4 < nPad4) ? ((const int4*)g_cnt)[idx4] : make_int4(0, 0, 0, 0);
    sSum[threadIdx.x] = v.x + v.y + v.z + v.w;
    __syncthreads();
    for (int d = SCAN_B / 2; d; d >>= 1) {
        if (threadIdx.x < d) sSum[threadIdx.x] += sSum[threadIdx.x + d];
        __syncthreads();
    }
    if (threadIdx.x == 0) g_bsum[blockIdx.x] = sSum[0];
}
__global__ void __launch_bounds__(256)
scanB_kernel(int nBlocks) {
    __shared__ int sV[256];
    int t = threadIdx.x;
    sV[t] = (t < nBlocks) ? g_bsum[t] : 0;
    __syncthreads();
    for (int d = 1; d < 256; d <<= 1) {
        int v = (t >= d) ? sV[t - d] : 0;
        __syncthreads();
        sV[t] += v;
        __syncthreads();
    }
    if (t < nBlocks) g_bpre[t] = sV[t] - g_bsum[t];
}
__global__ void __launch_bounds__(SCAN_B)
scanC_kernel(int nPad4) {
    __shared__ int sV[SCAN_B];
    int idx4 = blockIdx.x * SCAN_B + threadIdx.x;
    int4 v = (idx4 < nPad4) ? ((const int4*)g_cnt)[idx4] : make_int4(0, 0, 0, 0);
    int tsum = v.x + v.y + v.z + v.w;
    sV[threadIdx.x] = tsum;
    __syncthreads();
    for (int d = 1; d < SCAN_B; d <<= 1) {
        int u = (threadIdx.x >= d) ? sV[threadIdx.x - d] : 0;
        __syncthreads();
        sV[threadIdx.x] += u;
        __syncthreads();
    }
    int base = g_bpre[blockIdx.x] + sV[threadIdx.x] - tsum;
    if (idx4 < nPad4) {
        int4 o;
        o.x = base;
        o.y = base + v.x;
        o.z = base + v.x + v.y;
        o.w = base + v.x + v.y + v.z;
        ((int4*)g_off)[idx4] = o;
        ((int4*)g_cur)[idx4] = o;
    }
}

__global__ void fill_kernel(const int* __restrict__ iInd,
                            const int* __restrict__ jInd, int nE) {
    int e = blockIdx.x * blockDim.x + threadIdx.x;
    if (e >= nE) return;
    int I = iInd[e], J = jInd[e];
    float w2 = g_d2[I] * g_d2[J];
    unsigned short hb = __half_as_ushort(__float2half(w2));
    int pI = atomicAdd(&g_cur[I], 1);
    g_adj[pI] = ((unsigned)J << 16) | hb;              // +w2: use fmax(t,0)
    int pJ = atomicAdd(&g_cur[J], 1);
    g_adj[pJ] = ((unsigned)I << 16) | hb | 0x8000u;    // -w2: use fmin(t,0)
}

// ---------------- x0 = relu(K1Nopen @ xn) ----------------
__global__ void __launch_bounds__(256)
x0_kernel(const float* __restrict__ xn, const float* __restrict__ K1, int nN) {
    __shared__ float sK[NNIN * NOPEN];       // sK[c*64+o] = K1[o][c]
    __shared__ float sX[NNIN][256];
    for (int idx = threadIdx.x; idx < NOPEN * NNIN; idx += blockDim.x) {
        int o = idx >> 4, c = idx & 15;
        sK[c * NOPEN + o] = K1[idx];
    }
    int n0 = blockIdx.x * 256;
    for (int idx = threadIdx.x; idx < NNIN * 256; idx += blockDim.x) {
        int c = idx >> 8, nn = idx & 255;
        int n = n0 + nn;
        sX[c][nn] = (n < nN) ? xn[(size_t)c * nN + n] : 0.f;
    }
    __syncthreads();

    int n = n0 + threadIdx.x;
    if (n >= nN) return;
    float* dst = &g_x[(size_t)n * NOPEN];
#pragma unroll
    for (int half = 0; half < 2; half++) {
        float acc[32];
#pragma unroll
        for (int o = 0; o < 32; o++) acc[o] = 0.f;
#pragma unroll
        for (int c = 0; c < NNIN; c++) {
            float xc = sX[c][threadIdx.x];
#pragma unroll
            for (int o = 0; o < 32; o++)
                acc[o] += sK[c * NOPEN + half * 32 + o] * xc;
        }
#pragma unroll
        for (int o4 = 0; o4 < 8; o4++) {
            float4 r;
            r.x = fmaxf(acc[4 * o4 + 0], 0.f);
            r.y = fmaxf(acc[4 * o4 + 1], 0.f);
            r.z = fmaxf(acc[4 * o4 + 2], 0.f);
            r.w = fmaxf(acc[4 * o4 + 3], 0.f);
            ((float4*)dst)[half * 8 + o4] = r;
        }
    }
}

// ---------------- pre: p0 = fp8(KN1 @ x) (warp per node) ----------------
__global__ void __launch_bounds__(256)
pre_kernel(const float* __restrict__ KN1w, int nN) {
    __shared__ float sKp[64 * 66];           // sKp[k*66+o] = KN1[o][k]
    __shared__ float sRow[8][64];
    for (int idx = threadIdx.x; idx < 64 * 64; idx += blockDim.x) {
        int r = idx >> 6, c = idx & 63;
        sKp[c * 66 + r] = KN1w[idx];
    }
    __syncthreads();

    int lane = threadIdx.x & 31;
    int ws   = threadIdx.x >> 5;
    int n    = blockIdx.x * 8 + ws;
    if (n >= nN) return;
    int o0 = 2 * lane;

    float2 xv = *(const float2*)&g_x[(size_t)n * NOPEN + o0];
    sRow[ws][o0] = xv.x; sRow[ws][o0 + 1] = xv.y;
    __syncwarp();
    float p0 = 0.f, p1 = 0.f;
#pragma unroll 8
    for (int k = 0; k < 64; k++) {
        float xk = sRow[ws][k];
        float2 a = *(const float2*)&sKp[k * 66 + o0];
        p0 += a.x * xk;
        p1 += a.y * xk;
    }
    g_p8[0][(size_t)n * 32 + lane] = f32x2_to_fp8x2(p0, p1);
}

// ---------------- fused layer: 4 nodes per warp, 8 lanes per node ----------
__global__ void __launch_bounds__(256)
layer_kernel(const float* __restrict__ KN1w, const float* __restrict__ KC,
             float* __restrict__ out, int nN, int inbuf, int last) {
    __shared__ float sKy[64 * 66];           // sKy[k*66+o] = KN1[k][o]
    __shared__ float sKp[64 * 66];           // mid: KN1[o][k] ; last: KC[o][i]
    __shared__ float sS[8][4][64];           // per-warp, per-node staging
    const float* P2 = last ? KC : KN1w;
    for (int idx = threadIdx.x; idx < 64 * 64; idx += blockDim.x) {
        int r = idx >> 6, c = idx & 63;
        sKy[r * 66 + c] = KN1w[idx];
        sKp[c * 66 + r] = P2[idx];
    }
    __syncthreads();

    const unsigned short* pin  = g_p8[inbuf];
    unsigned short*       pout = g_p8[inbuf ^ 1];

    int lane = threadIdx.x & 31;
    int ws   = threadIdx.x >> 5;
    int gi   = lane >> 3;                   // group (node) within warp, 0..3
    int li   = lane & 7;                    // lane within group
    int nBase = (blockIdx.x * 8 + ws) * 4;  // first node of this warp
    int n = nBase + gi;
    bool valid = (n < nN);

    int beg = 0, cnt = 0;
    if (valid) { beg = g_off[n]; cnt = g_cnt[n]; }

    // p_self: 8 dims per lane (4 fp8x2 = uint2)
    uint2 psu = make_uint2(0u, 0u);
    if (valid) psu = __ldg((const uint2*)(pin + (size_t)n * 32) + li);
    __half2 ps[4];
    fp8x4_to_2half2(psu.x, ps[0], ps[1]);
    fp8x4_to_2half2(psu.y, ps[2], ps[3]);

    // max cnt over warp
    int cmax = cnt;
#pragma unroll
    for (int o = 16; o; o >>= 1)
        cmax = max(cmax, __shfl_xor_sync(0xffffffffu, cmax, o));

    const __half2 zero2 = __float2half2_rn(0.f);
    __half2 acc[4];
#pragma unroll
    for (int i = 0; i < 4; i++) acc[i] = zero2;

    for (int t0 = 0; t0 < cmax; t0 += 8) {
        int idx = t0 + li;
        unsigned v = (idx < cnt) ? __ldg(&g_adj[beg + idx]) : 0u;  // w=+0 -> 0
        unsigned vv[8];
        uint2 pbv[8];
#pragma unroll
        for (int k = 0; k < 8; k++)
            vv[k] = __shfl_sync(0xffffffffu, v, (gi << 3) | k);
#pragma unroll
        for (int k = 0; k < 8; k++)
            pbv[k] = __ldg((const uint2*)(pin + (size_t)(vv[k] >> 16) * 32) + li);
#pragma unroll
        for (int k = 0; k < 8; k++) {
            __half2 pb0, pb1, pb2, pb3;
            fp8x4_to_2half2(pbv[k].x, pb0, pb1);
            fp8x4_to_2half2(pbv[k].y, pb2, pb3);
            __half2 w2h = __half2half2(
                __ushort_as_half((unsigned short)(vv[k] & 0x7fffu)));
            bool neg = (vv[k] & 0x8000u) != 0;
            __half2 t0h = __hsub2(ps[0], pb0);
            __half2 t1h = __hsub2(ps[1], pb1);
            __half2 t2h = __hsub2(ps[2], pb2);
            __half2 t3h = __hsub2(ps[3], pb3);
            __half2 d0 = neg ? __hmin2(t0h, zero2) : __hmax2(t0h, zero2);
            __half2 d1 = neg ? __hmin2(t1h, zero2) : __hmax2(t1h, zero2);
            __half2 d2 = neg ? __hmin2(t2h, zero2) : __hmax2(t2h, zero2);
            __half2 d3 = neg ? __hmin2(t3h, zero2) : __hmax2(t3h, zero2);
            acc[0] = __hfma2(d0, w2h, acc[0]);
            acc[1] = __hfma2(d1, w2h, acc[1]);
            acc[2] = __hfma2(d2, w2h, acc[2]);
            acc[3] = __hfma2(d3, w2h, acc[3]);
        }
    }

    // stage s rows: lane li holds dims 8*li .. 8*li+7 of node gi
#pragma unroll
    for (int i = 0; i < 4; i++) {
        float2 f = __half22float2(acc[i]);
        *(float2*)&sS[ws][gi][li * 8 + 2 * i] = f;
    }
    __syncwarp();

    // epilogue: 4 nodes sequentially, full-warp matvecs
    int o0 = 2 * lane;
#pragma unroll
    for (int q = 0; q < 4; q++) {
        int nq = nBase + q;
        if (nq >= nN) break;
        float y0 = 0.f, y1 = 0.f;
#pragma unroll 8
        for (int k = 0; k < 64; k++) {
            float sk = sS[ws][q][k];
            float2 av = *(const float2*)&sKy[k * 66 + o0];
            y0 += av.x * sk;
            y1 += av.y * sk;
        }
        size_t off = (size_t)nq * NOPEN + o0;
        float2 xv = *(const float2*)&g_x[off];
        xv.x -= DTH * y0;
        xv.y -= DTH * y1;

        __syncwarp();
        sS[ws][q][o0] = xv.x; sS[ws][q][o0 + 1] = xv.y;
        __syncwarp();
        float v0 = 0.f, v1 = 0.f;
#pragma unroll 8
        for (int k = 0; k < 64; k++) {
            float xk = sS[ws][q][k];
            float2 av = *(const float2*)&sKp[k * 66 + o0];
            v0 += av.x * xk;
            v1 += av.y * xk;
        }

        if (!last) {
            *(float2*)&g_x[off] = xv;
            pout[(size_t)nq * 32 + lane] = f32x2_to_fp8x2(v0, v1);
        } else {
            float m = fmaxf(v0, v1);
#pragma unroll
            for (int o = 16; o; o >>= 1)
                m = fmaxf(m, __shfl_xor_sync(0xffffffffu, m, o));
            float s = expf(v0 - m) + expf(v1 - m);
#pragma unroll
            for (int o = 16; o; o >>= 1)
                s += __shfl_xor_sync(0xffffffffu, s, o);
            float lse = m + logf(s);
            float2 r;
            r.x = v0 - lse;
            r.y = v1 - lse;
            *(float2*)&out[(size_t)nq * NOPEN + o0] = r;
        }
    }
}

// ---------------- launch ----------------
extern "C" void kernel_launch(void* const* d_in, const int* in_sizes, int n_in,
                              void* d_out, int out_size) {
    const float* xn   = (const float*)d_in[0];
    const int*   iInd = (const int*)d_in[1];
    const int*   jInd = (const int*)d_in[2];
    int base = 3;
    if (n_in >= 7 && in_sizes[3] == 1) base = 4;
    const float* K1  = (const float*)d_in[base];
    const float* KN1 = (const float*)d_in[base + 1];
    const float* KC  = (const float*)d_in[base + 2];

    int nN = in_sizes[0] / NNIN;
    int nE = in_sizes[1];

    int nodeBlocks8 = (nN + 7) / 8;          // warp-per-node kernels
    int layerBlocks = (nN + 31) / 32;        // 4 nodes/warp, 8 warps/block
    int nb256 = (nN + 255) / 256;
    int eb256 = (nE + 255) / 256;
    int nPad4 = (nN + 3) / 4;
    int scanBlocks = (nPad4 + SCAN_B - 1) / SCAN_B;

    // CSR build + norm
    init_kernel<<<nb256, 256>>>(nN);
    count_kernel<<<eb256, 256>>>(iInd, jInd, nE);
    d2_kernel<<<nb256, 256>>>(nN);
    scanA_kernel<<<scanBlocks, SCAN_B>>>(nPad4);
    scanB_kernel<<<1, 256>>>(scanBlocks);
    scanC_kernel<<<scanBlocks, SCAN_B>>>(nPad4);
    fill_kernel<<<eb256, 256>>>(iInd, jInd, nE);

    // network
    x0_kernel<<<nb256, 256>>>(xn, K1, nN);
    pre_kernel<<<nodeBlocks8, 256>>>(KN1, nN);
    for (int l = 0; l < 4; l++)
        layer_kernel<<<layerBlocks, 256>>>(KN1, KC, (float*)d_out, nN, l & 1,
                                           l == 3 ? 1 : 0);
}

// round 12
// speedup vs baseline: 1.1725x; 1.0467x over previous
#include <cuda_runtime.h>
#include <cuda_fp16.h>
#include <math.h>

// ---------------- problem constants ----------------
#define NOPEN 64
#define NNIN  16
#define MAXN  65536
#define MAXE  4000000           // capacity for 2*nE incident entries
#define DTH   0.025f            // dt*H = (1/4)*0.1
#define SCAN_B 256

// ---------------- device scratch ----------------
__device__ float          g_x[(size_t)MAXN * NOPEN];   // node features (f32)
__device__ unsigned short g_p8[2][(size_t)MAXN * 32];  // ping-pong p (e4m3x2/lane)
__device__ float          g_d2[MAXN];                  // 1/deg
__device__ int            g_deg[MAXN];
__device__ int            g_cnt[MAXN];                 // incident count
__device__ int            g_off[MAXN];                 // CSR offsets
__device__ int            g_cur[MAXN];                 // fill cursors
__device__ unsigned       g_adj[MAXE];                 // (nbr<<16) | f16bits(+-w2)
__device__ int            g_bsum[256];
__device__ int            g_bpre[256];

// ---------------- fp8 helpers ----------------
static __device__ __forceinline__ unsigned short f32x2_to_fp8x2(float lo, float hi) {
    unsigned short u;
    asm("cvt.rn.satfinite.e4m3x2.f32 %0, %1, %2;" : "=h"(u) : "f"(hi), "f"(lo));
    return u;
}
// one u32 = 4 fp8 = 2 fp8x2 -> two half2
static __device__ __forceinline__ void fp8x4_to_2half2(unsigned u, __half2& a, __half2& b) {
    unsigned r0, r1;
    asm("{\n\t"
        ".reg .b16 l, h;\n\t"
        "mov.b32 {l, h}, %2;\n\t"
        "cvt.rn.f16x2.e4m3x2 %0, l;\n\t"
        "cvt.rn.f16x2.e4m3x2 %1, h;\n\t"
        "}" : "=r"(r0), "=r"(r1) : "r"(u));
    a = *(__half2*)&r0;
    b = *(__half2*)&r1;
}

// ---------------- init / fused count ----------------
__global__ void init_kernel(int nN) {
    int i = blockIdx.x * blockDim.x + threadIdx.x;
    if (i < nN) { g_deg[i] = 1; g_cnt[i] = 0; }
}
__global__ void count_kernel(const int* __restrict__ iInd,
                             const int* __restrict__ jInd, int nE) {
    int e = blockIdx.x * blockDim.x + threadIdx.x;
    if (e >= nE) return;
    int I = iInd[e], J = jInd[e];
    atomicAdd(&g_deg[J], 1);
    atomicAdd(&g_cnt[I], 1);
    atomicAdd(&g_cnt[J], 1);
}
__global__ void d2_kernel(int nN) {
    int i = blockIdx.x * blockDim.x + threadIdx.x;
    if (i < nN) g_d2[i] = 1.0f / (float)g_deg[i];
}

// ---------------- 3-phase scan (coalesced) ----------------
__global__ void __launch_bounds__(SCAN_B)
scanA_kernel(int nPad4) {
    __shared__ int sSum[SCAN_B];
    int idx4 = blockIdx.x * SCAN_B + threadIdx.x;
    int4 v = (idx4 < nPad4) ? ((const int4*)g_cnt)[idx4] : make_int4(0, 0, 0, 0);
    sSum[threadIdx.x] = v.x + v.y + v.z + v.w;
    __syncthreads();
    for (int d = SCAN_B / 2; d; d >>= 1) {
        if (threadIdx.x < d) sSum[threadIdx.x] += sSum[threadIdx.x + d];
        __syncthreads();
    }
    if (threadIdx.x == 0) g_bsum[blockIdx.x] = sSum[0];
}
__global__ void __launch_bounds__(256)
scanB_kernel(int nBlocks) {
    __shared__ int sV[256];
    int t = threadIdx.x;
    sV[t] = (t < nBlocks) ? g_bsum[t] : 0;
    __syncthreads();
    for (int d = 1; d < 256; d <<= 1) {
        int v = (t >= d) ? sV[t - d] : 0;
        __syncthreads();
        sV[t] += v;
        __syncthreads();
    }
    if (t < nBlocks) g_bpre[t] = sV[t] - g_bsum[t];
}
__global__ void __launch_bounds__(SCAN_B)
scanC_kernel(int nPad4) {
    __shared__ int sV[SCAN_B];
    int idx4 = blockIdx.x * SCAN_B + threadIdx.x;
    int4 v = (idx4 < nPad4) ? ((const int4*)g_cnt)[idx4] : make_int4(0, 0, 0, 0);
    int tsum = v.x + v.y + v.z + v.w;
    sV[threadIdx.x] = tsum;
    __syncthreads();
    for (int d = 1; d < SCAN_B; d <<= 1) {
        int u = (threadIdx.x >= d) ? sV[threadIdx.x - d] : 0;
        __syncthreads();
        sV[threadIdx.x] += u;
        __syncthreads();
    }
    int base = g_bpre[blockIdx.x] + sV[threadIdx.x] - tsum;
    if (idx4 < nPad4) {
        int4 o;
        o.x = base;
        o.y = base + v.x;
        o.z = base + v.x + v.y;
        o.w = base + v.x + v.y + v.z;
        ((int4*)g_off)[idx4] = o;
        ((int4*)g_cur)[idx4] = o;
    }
}

__global__ void fill_kernel(const int* __restrict__ iInd,
                            const int* __restrict__ jInd, int nE) {
    int e = blockIdx.x * blockDim.x + threadIdx.x;
    if (e >= nE) return;
    int I = iInd[e], J = jInd[e];
    float w2 = g_d2[I] * g_d2[J];
    unsigned short hb = __half_as_ushort(__float2half(w2));
    int pI = atomicAdd(&g_cur[I], 1);
    g_adj[pI] = ((unsigned)J << 16) | hb;              // +w2: use fmax(t,0)
    int pJ = atomicAdd(&g_cur[J], 1);
    g_adj[pJ] = ((unsigned)I << 16) | hb | 0x8000u;    // -w2: use fmin(t,0)
}

// ---------------- x0 = relu(K1Nopen @ xn) ----------------
__global__ void __launch_bounds__(256)
x0_kernel(const float* __restrict__ xn, const float* __restrict__ K1, int nN) {
    __shared__ float sK[NNIN * NOPEN];       // sK[c*64+o] = K1[o][c]
    __shared__ float sX[NNIN][256];
    for (int idx = threadIdx.x; idx < NOPEN * NNIN; idx += blockDim.x) {
        int o = idx >> 4, c = idx & 15;
        sK[c * NOPEN + o] = K1[idx];
    }
    int n0 = blockIdx.x * 256;
    for (int idx = threadIdx.x; idx < NNIN * 256; idx += blockDim.x) {
        int c = idx >> 8, nn = idx & 255;
        int n = n0 + nn;
        sX[c][nn] = (n < nN) ? xn[(size_t)c * nN + n] : 0.f;
    }
    __syncthreads();

    int n = n0 + threadIdx.x;
    if (n >= nN) return;
    float* dst = &g_x[(size_t)n * NOPEN];
#pragma unroll
    for (int half = 0; half < 2; half++) {
        float acc[32];
#pragma unroll
        for (int o = 0; o < 32; o++) acc[o] = 0.f;
#pragma unroll
        for (int c = 0; c < NNIN; c++) {
            float xc = sX[c][threadIdx.x];
#pragma unroll
            for (int o = 0; o < 32; o++)
                acc[o] += sK[c * NOPEN + half * 32 + o] * xc;
        }
#pragma unroll
        for (int o4 = 0; o4 < 8; o4++) {
            float4 r;
            r.x = fmaxf(acc[4 * o4 + 0], 0.f);
            r.y = fmaxf(acc[4 * o4 + 1], 0.f);
            r.z = fmaxf(acc[4 * o4 + 2], 0.f);
            r.w = fmaxf(acc[4 * o4 + 3], 0.f);
            ((float4*)dst)[half * 8 + o4] = r;
        }
    }
}

// ---------------- pre: p0 = fp8(KN1 @ x) (warp per node) ----------------
__global__ void __launch_bounds__(256)
pre_kernel(const float* __restrict__ KN1w, int nN) {
    __shared__ float sKp[64 * 66];           // sKp[k*66+o] = KN1[o][k]
    __shared__ float sRow[8][64];
    for (int idx = threadIdx.x; idx < 64 * 64; idx += blockDim.x) {
        int r = idx >> 6, c = idx & 63;
        sKp[c * 66 + r] = KN1w[idx];
    }
    __syncthreads();

    int lane = threadIdx.x & 31;
    int ws   = threadIdx.x >> 5;
    int n    = blockIdx.x * 8 + ws;
    if (n >= nN) return;
    int o0 = 2 * lane;

    float2 xv = *(const float2*)&g_x[(size_t)n * NOPEN + o0];
    sRow[ws][o0] = xv.x; sRow[ws][o0 + 1] = xv.y;
    __syncwarp();
    float p0 = 0.f, p1 = 0.f;
#pragma unroll 8
    for (int k = 0; k < 64; k++) {
        float xk = sRow[ws][k];
        float2 a = *(const float2*)&sKp[k * 66 + o0];
        p0 += a.x * xk;
        p1 += a.y * xk;
    }
    g_p8[0][(size_t)n * 32 + lane] = f32x2_to_fp8x2(p0, p1);
}

// ---------------- fused layer: 4 nodes/warp, 8 lanes/node, 16-deep loads ---
__global__ void __launch_bounds__(256)
layer_kernel(const float* __restrict__ KN1w, const float* __restrict__ KC,
             float* __restrict__ out, int nN, int inbuf, int last) {
    __shared__ __half sKy[64 * 66];          // sKy[k*66+o] = KN1[k][o]   (f16)
    __shared__ __half sKp[64 * 66];          // mid: KN1[o][k]; last: KC[o][i]
    __shared__ float sS[8][4][64];           // per-warp, per-node staging
    const float* P2 = last ? KC : KN1w;
    for (int idx = threadIdx.x; idx < 64 * 64; idx += blockDim.x) {
        int r = idx >> 6, c = idx & 63;
        sKy[r * 66 + c] = __float2half(KN1w[idx]);
        sKp[c * 66 + r] = __float2half(P2[idx]);
    }
    __syncthreads();

    const unsigned short* pin  = g_p8[inbuf];
    unsigned short*       pout = g_p8[inbuf ^ 1];

    int lane = threadIdx.x & 31;
    int ws   = threadIdx.x >> 5;
    int gi   = lane >> 3;                   // group (node) within warp, 0..3
    int li   = lane & 7;                    // lane within group
    int nBase = (blockIdx.x * 8 + ws) * 4;
    int n = nBase + gi;
    bool valid = (n < nN);

    int beg = 0, cnt = 0;
    if (valid) { beg = g_off[n]; cnt = g_cnt[n]; }

    uint2 psu = make_uint2(0u, 0u);
    if (valid) psu = __ldg((const uint2*)(pin + (size_t)n * 32) + li);
    __half2 ps[4];
    fp8x4_to_2half2(psu.x, ps[0], ps[1]);
    fp8x4_to_2half2(psu.y, ps[2], ps[3]);

    int cmax = cnt;
#pragma unroll
    for (int o = 16; o; o >>= 1)
        cmax = max(cmax, __shfl_xor_sync(0xffffffffu, cmax, o));

    const __half2 zero2 = __float2half2_rn(0.f);
    __half2 acc[4];
#pragma unroll
    for (int i = 0; i < 4; i++) acc[i] = zero2;

    for (int t0 = 0; t0 < cmax; t0 += 16) {
        int ia = t0 + li, ib = t0 + 8 + li;
        unsigned va = (ia < cnt) ? __ldg(&g_adj[beg + ia]) : 0u;
        unsigned vb = (ib < cnt) ? __ldg(&g_adj[beg + ib]) : 0u;
        unsigned vv[16];
        uint2 pbv[16];
#pragma unroll
        for (int k = 0; k < 8; k++) {
            vv[k]     = __shfl_sync(0xffffffffu, va, (gi << 3) | k);
            vv[8 + k] = __shfl_sync(0xffffffffu, vb, (gi << 3) | k);
        }
#pragma unroll
        for (int k = 0; k < 16; k++)
            pbv[k] = __ldg((const uint2*)(pin + (size_t)(vv[k] >> 16) * 32) + li);
#pragma unroll
        for (int k = 0; k < 16; k++) {
            __half2 pb0, pb1, pb2, pb3;
            fp8x4_to_2half2(pbv[k].x, pb0, pb1);
            fp8x4_to_2half2(pbv[k].y, pb2, pb3);
            __half2 w2h = __half2half2(
                __ushort_as_half((unsigned short)(vv[k] & 0x7fffu)));
            bool neg = (vv[k] & 0x8000u) != 0;
            __half2 t0h = __hsub2(ps[0], pb0);
            __half2 t1h = __hsub2(ps[1], pb1);
            __half2 t2h = __hsub2(ps[2], pb2);
            __half2 t3h = __hsub2(ps[3], pb3);
            __half2 d0 = neg ? __hmin2(t0h, zero2) : __hmax2(t0h, zero2);
            __half2 d1 = neg ? __hmin2(t1h, zero2) : __hmax2(t1h, zero2);
            __half2 d2 = neg ? __hmin2(t2h, zero2) : __hmax2(t2h, zero2);
            __half2 d3 = neg ? __hmin2(t3h, zero2) : __hmax2(t3h, zero2);
            acc[0] = __hfma2(d0, w2h, acc[0]);
            acc[1] = __hfma2(d1, w2h, acc[1]);
            acc[2] = __hfma2(d2, w2h, acc[2]);
            acc[3] = __hfma2(d3, w2h, acc[3]);
        }
    }

#pragma unroll
    for (int i = 0; i < 4; i++) {
        float2 f = __half22float2(acc[i]);
        *(float2*)&sS[ws][gi][li * 8 + 2 * i] = f;
    }
    __syncwarp();

    int o0 = 2 * lane;
#pragma unroll
    for (int q = 0; q < 4; q++) {
        int nq = nBase + q;
        if (nq >= nN) break;
        float y0 = 0.f, y1 = 0.f;
#pragma unroll 8
        for (int k = 0; k < 64; k++) {
            float sk = sS[ws][q][k];
            float2 av = __half22float2(*(const __half2*)&sKy[k * 66 + o0]);
            y0 += av.x * sk;
            y1 += av.y * sk;
        }
        size_t off = (size_t)nq * NOPEN + o0;
        float2 xv = *(const float2*)&g_x[off];
        xv.x -= DTH * y0;
        xv.y -= DTH * y1;

        __syncwarp();
        sS[ws][q][o0] = xv.x; sS[ws][q][o0 + 1] = xv.y;
        __syncwarp();
        float v0 = 0.f, v1 = 0.f;
#pragma unroll 8
        for (int k = 0; k < 64; k++) {
            float xk = sS[ws][q][k];
            float2 av = __half22float2(*(const __half2*)&sKp[k * 66 + o0]);
            v0 += av.x * xk;
            v1 += av.y * xk;
        }

        if (!last) {
            *(float2*)&g_x[off] = xv;
            pout[(size_t)nq * 32 + lane] = f32x2_to_fp8x2(v0, v1);
        } else {
            float m = fmaxf(v0, v1);
#pragma unroll
            for (int o = 16; o; o >>= 1)
                m = fmaxf(m, __shfl_xor_sync(0xffffffffu, m, o));
            float s = expf(v0 - m) + expf(v1 - m);
#pragma unroll
            for (int o = 16; o; o >>= 1)
                s += __shfl_xor_sync(0xffffffffu, s, o);
            float lse = m + logf(s);
            float2 r;
            r.x = v0 - lse;
            r.y = v1 - lse;
            *(float2*)&out[(size_t)nq * NOPEN + o0] = r;
        }
    }
}

// ---------------- launch ----------------
extern "C" void kernel_launch(void* const* d_in, const int* in_sizes, int n_in,
                              void* d_out, int out_size) {
    const float* xn   = (const float*)d_in[0];
    const int*   iInd = (const int*)d_in[1];
    const int*   jInd = (const int*)d_in[2];
    int base = 3;
    if (n_in >= 7 && in_sizes[3] == 1) base = 4;
    const float* K1  = (const float*)d_in[base];
    const float* KN1 = (const float*)d_in[base + 1];
    const float* KC  = (const float*)d_in[base + 2];

    int nN = in_sizes[0] / NNIN;
    int nE = in_sizes[1];

    int nodeBlocks8 = (nN + 7) / 8;
    int layerBlocks = (nN + 31) / 32;
    int nb256 = (nN + 255) / 256;
    int eb256 = (nE + 255) / 256;
    int nPad4 = (nN + 3) / 4;
    int scanBlocks = (nPad4 + SCAN_B - 1) / SCAN_B;

    // CSR build + norm
    init_kernel<<<nb256, 256>>>(nN);
    count_kernel<<<eb256, 256>>>(iInd, jInd, nE);
    d2_kernel<<<nb256, 256>>>(nN);
    scanA_kernel<<<scanBlocks, SCAN_B>>>(nPad4);
    scanB_kernel<<<1, 256>>>(scanBlocks);
    scanC_kernel<<<scanBlocks, SCAN_B>>>(nPad4);
    fill_kernel<<<eb256, 256>>>(iInd, jInd, nE);

    // network
    x0_kernel<<<nb256, 256>>>(xn, K1, nN);
    pre_kernel<<<nodeBlocks8, 256>>>(KN1, nN);
    for (int l = 0; l < 4; l++)
        layer_kernel<<<layerBlocks, 256>>>(KN1, KC, (float*)d_out, nN, l & 1,
                                           l == 3 ? 1 : 0);
}

// round 13
// speedup vs baseline: 1.1743x; 1.0015x over previous
#include <cuda_runtime.h>
#include <cuda_fp16.h>
#include <math.h>

// ---------------- problem constants ----------------
#define NOPEN 64
#define NNIN  16
#define MAXN  65536
#define MAXE  4000000           // capacity for 2*nE incident entries
#define DTH   0.025f            // dt*H = (1/4)*0.1
#define SCAN_B 256

// ---------------- device scratch ----------------
__device__ float    g_x[(size_t)MAXN * NOPEN];   // node features (f32)
__device__ __half2  g_p2[2][(size_t)MAXN * 32];  // ping-pong p = KN1 @ x (f16)
__device__ float    g_d2[MAXN];                  // 1/deg
__device__ int      g_deg[MAXN];
__device__ int      g_cnt[MAXN];                 // incident count
__device__ int      g_off[MAXN];                 // CSR offsets
__device__ int      g_cur[MAXN];                 // fill cursors
__device__ unsigned g_adj[MAXE];                 // (nbr<<16) | f16bits(+-w2)
__device__ int      g_bsum[256];
__device__ int      g_bpre[256];

// ---------------- init / fused count ----------------
__global__ void init_kernel(int nN) {
    int i = blockIdx.x * blockDim.x + threadIdx.x;
    if (i < nN) { g_deg[i] = 1; g_cnt[i] = 0; }
}
__global__ void count_kernel(const int* __restrict__ iInd,
                             const int* __restrict__ jInd, int nE) {
    int e = blockIdx.x * blockDim.x + threadIdx.x;
    if (e >= nE) return;
    int I = iInd[e], J = jInd[e];
    atomicAdd(&g_deg[J], 1);
    atomicAdd(&g_cnt[I], 1);
    atomicAdd(&g_cnt[J], 1);
}
__global__ void d2_kernel(int nN) {
    int i = blockIdx.x * blockDim.x + threadIdx.x;
    if (i < nN) g_d2[i] = 1.0f / (float)g_deg[i];
}

// ---------------- 3-phase scan (coalesced) ----------------
__global__ void __launch_bounds__(SCAN_B)
scanA_kernel(int nPad4) {
    __shared__ int sSum[SCAN_B];
    int idx4 = blockIdx.x * SCAN_B + threadIdx.x;
    int4 v = (idx4 < nPad4) ? ((const int4*)g_cnt)[idx4] : make_int4(0, 0, 0, 0);
    sSum[threadIdx.x] = v.x + v.y + v.z + v.w;
    __syncthreads();
    for (int d = SCAN_B / 2; d; d >>= 1) {
        if (threadIdx.x < d) sSum[threadIdx.x] += sSum[threadIdx.x + d];
        __syncthreads();
    }
    if (threadIdx.x == 0) g_bsum[blockIdx.x] = sSum[0];
}
__global__ void __launch_bounds__(256)
scanB_kernel(int nBlocks) {
    __shared__ int sV[256];
    int t = threadIdx.x;
    sV[t] = (t < nBlocks) ? g_bsum[t] : 0;
    __syncthreads();
    for (int d = 1; d < 256; d <<= 1) {
        int v = (t >= d) ? sV[t - d] : 0;
        __syncthreads();
        sV[t] += v;
        __syncthreads();
    }
    if (t < nBlocks) g_bpre[t] = sV[t] - g_bsum[t];
}
__global__ void __launch_bounds__(SCAN_B)
scanC_kernel(int nPad4) {
    __shared__ int sV[SCAN_B];
    int idx4 = blockIdx.x * SCAN_B + threadIdx.x;
    int4 v = (idx4 < nPad4) ? ((const int4*)g_cnt)[idx4] : make_int4(0, 0, 0, 0);
    int tsum = v.x + v.y + v.z + v.w;
    sV[threadIdx.x] = tsum;
    __syncthreads();
    for (int d = 1; d < SCAN_B; d <<= 1) {
        int u = (threadIdx.x >= d) ? sV[threadIdx.x - d] : 0;
        __syncthreads();
        sV[threadIdx.x] += u;
        __syncthreads();
    }
    int base = g_bpre[blockIdx.x] + sV[threadIdx.x] - tsum;
    if (idx4 < nPad4) {
        int4 o;
        o.x = base;
        o.y = base + v.x;
        o.z = base + v.x + v.y;
        o.w = base + v.x + v.y + v.z;
        ((int4*)g_off)[idx4] = o;
        ((int4*)g_cur)[idx4] = o;
    }
}

__global__ void fill_kernel(const int* __restrict__ iInd,
                            const int* __restrict__ jInd, int nE) {
    int e = blockIdx.x * blockDim.x + threadIdx.x;
    if (e >= nE) return;
    int I = iInd[e], J = jInd[e];
    float w2 = g_d2[I] * g_d2[J];
    unsigned short hb = __half_as_ushort(__float2half(w2));
    int pI = atomicAdd(&g_cur[I], 1);
    g_adj[pI] = ((unsigned)J << 16) | hb;              // +w2: use fmax(t,0)
    int pJ = atomicAdd(&g_cur[J], 1);
    g_adj[pJ] = ((unsigned)I << 16) | hb | 0x8000u;    // -w2: use fmin(t,0)
}

// ---------------- x0 = relu(K1Nopen @ xn) ----------------
__global__ void __launch_bounds__(256)
x0_kernel(const float* __restrict__ xn, const float* __restrict__ K1, int nN) {
    __shared__ float sK[NNIN * NOPEN];       // sK[c*64+o] = K1[o][c]
    __shared__ float sX[NNIN][256];
    for (int idx = threadIdx.x; idx < NOPEN * NNIN; idx += blockDim.x) {
        int o = idx >> 4, c = idx & 15;
        sK[c * NOPEN + o] = K1[idx];
    }
    int n0 = blockIdx.x * 256;
    for (int idx = threadIdx.x; idx < NNIN * 256; idx += blockDim.x) {
        int c = idx >> 8, nn = idx & 255;
        int n = n0 + nn;
        sX[c][nn] = (n < nN) ? xn[(size_t)c * nN + n] : 0.f;
    }
    __syncthreads();

    int n = n0 + threadIdx.x;
    if (n >= nN) return;
    float* dst = &g_x[(size_t)n * NOPEN];
#pragma unroll
    for (int half = 0; half < 2; half++) {
        float acc[32];
#pragma unroll
        for (int o = 0; o < 32; o++) acc[o] = 0.f;
#pragma unroll
        for (int c = 0; c < NNIN; c++) {
            float xc = sX[c][threadIdx.x];
#pragma unroll
            for (int o = 0; o < 32; o++)
                acc[o] += sK[c * NOPEN + half * 32 + o] * xc;
        }
#pragma unroll
        for (int o4 = 0; o4 < 8; o4++) {
            float4 r;
            r.x = fmaxf(acc[4 * o4 + 0], 0.f);
            r.y = fmaxf(acc[4 * o4 + 1], 0.f);
            r.z = fmaxf(acc[4 * o4 + 2], 0.f);
            r.w = fmaxf(acc[4 * o4 + 3], 0.f);
            ((float4*)dst)[half * 8 + o4] = r;
        }
    }
}

// ---------------- pre: p0 = f16(KN1 @ x) (warp per node) ----------------
__global__ void __launch_bounds__(256)
pre_kernel(const float* __restrict__ KN1w, int nN) {
    __shared__ float sKp[64 * 66];           // sKp[k*66+o] = KN1[o][k]
    __shared__ float sRow[8][64];
    for (int idx = threadIdx.x; idx < 64 * 64; idx += blockDim.x) {
        int r = idx >> 6, c = idx & 63;
        sKp[c * 66 + r] = KN1w[idx];
    }
    __syncthreads();

    int lane = threadIdx.x & 31;
    int ws   = threadIdx.x >> 5;
    int n    = blockIdx.x * 8 + ws;
    if (n >= nN) return;
    int o0 = 2 * lane;

    float2 xv = *(const float2*)&g_x[(size_t)n * NOPEN + o0];
    sRow[ws][o0] = xv.x; sRow[ws][o0 + 1] = xv.y;
    __syncwarp();
    float p0 = 0.f, p1 = 0.f;
#pragma unroll 8
    for (int k = 0; k < 64; k++) {
        float xk = sRow[ws][k];
        float2 a = *(const float2*)&sKp[k * 66 + o0];
        p0 += a.x * xk;
        p1 += a.y * xk;
    }
    g_p2[0][(size_t)n * 32 + lane] = __floats2half2_rn(p0, p1);
}

// ---------------- fused layer: 4 nodes/warp, 8 lanes/node, f16 uint4 rows --
__global__ void __launch_bounds__(256)
layer_kernel(const float* __restrict__ KN1w, const float* __restrict__ KC,
             float* __restrict__ out, int nN, int inbuf, int last) {
    __shared__ __half sKy[64 * 66];          // sKy[k*66+o] = KN1[k][o]
    __shared__ __half sKp[64 * 66];          // mid: KN1[o][k]; last: KC[o][i]
    __shared__ float sS[8][4][64];           // per-warp, per-node staging
    const float* P2 = last ? KC : KN1w;
    for (int idx = threadIdx.x; idx < 64 * 64; idx += blockDim.x) {
        int r = idx >> 6, c = idx & 63;
        sKy[r * 66 + c] = __float2half(KN1w[idx]);
        sKp[c * 66 + r] = __float2half(P2[idx]);
    }
    __syncthreads();

    const __half2* pin  = g_p2[inbuf];
    __half2*       pout = g_p2[inbuf ^ 1];

    int lane = threadIdx.x & 31;
    int ws   = threadIdx.x >> 5;
    int gi   = lane >> 3;                   // group (node) within warp, 0..3
    int li   = lane & 7;                    // lane within group
    int nBase = (blockIdx.x * 8 + ws) * 4;
    int n = nBase + gi;
    bool valid = (n < nN);

    int beg = 0, cnt = 0;
    if (valid) { beg = g_off[n]; cnt = g_cnt[n]; }

    // p_self: lane li holds dims 8li..8li+7 as 4 half2 (uint4)
    uint4 psu = make_uint4(0u, 0u, 0u, 0u);
    if (valid) psu = __ldg((const uint4*)(pin + (size_t)n * 32) + li);
    __half2 ps[4];
    ps[0] = *(__half2*)&psu.x; ps[1] = *(__half2*)&psu.y;
    ps[2] = *(__half2*)&psu.z; ps[3] = *(__half2*)&psu.w;

    int cmax = cnt;
#pragma unroll
    for (int o = 16; o; o >>= 1)
        cmax = max(cmax, __shfl_xor_sync(0xffffffffu, cmax, o));

    const __half2 zero2 = __float2half2_rn(0.f);
    __half2 acc[4];
#pragma unroll
    for (int i = 0; i < 4; i++) acc[i] = zero2;

    for (int t0 = 0; t0 < cmax; t0 += 16) {
        int ia = t0 + li, ib = t0 + 8 + li;
        unsigned va = (ia < cnt) ? __ldg(&g_adj[beg + ia]) : 0u;
        unsigned vb = (ib < cnt) ? __ldg(&g_adj[beg + ib]) : 0u;
#pragma unroll
        for (int h = 0; h < 2; h++) {
            unsigned src = h ? vb : va;
            unsigned vv[8];
            uint4 pbv[8];
#pragma unroll
            for (int k = 0; k < 8; k++)
                vv[k] = __shfl_sync(0xffffffffu, src, (gi << 3) | k);
#pragma unroll
            for (int k = 0; k < 8; k++)
                pbv[k] = __ldg((const uint4*)(pin + (size_t)(vv[k] >> 16) * 32) + li);
#pragma unroll
            for (int k = 0; k < 8; k++) {
                __half2 w2h = __half2half2(
                    __ushort_as_half((unsigned short)(vv[k] & 0x7fffu)));
                bool neg = (vv[k] & 0x8000u) != 0;
                __half2 t0h = __hsub2(ps[0], *(__half2*)&pbv[k].x);
                __half2 t1h = __hsub2(ps[1], *(__half2*)&pbv[k].y);
                __half2 t2h = __hsub2(ps[2], *(__half2*)&pbv[k].z);
                __half2 t3h = __hsub2(ps[3], *(__half2*)&pbv[k].w);
                __half2 d0 = neg ? __hmin2(t0h, zero2) : __hmax2(t0h, zero2);
                __half2 d1 = neg ? __hmin2(t1h, zero2) : __hmax2(t1h, zero2);
                __half2 d2 = neg ? __hmin2(t2h, zero2) : __hmax2(t2h, zero2);
                __half2 d3 = neg ? __hmin2(t3h, zero2) : __hmax2(t3h, zero2);
                acc[0] = __hfma2(d0, w2h, acc[0]);
                acc[1] = __hfma2(d1, w2h, acc[1]);
                acc[2] = __hfma2(d2, w2h, acc[2]);
                acc[3] = __hfma2(d3, w2h, acc[3]);
            }
        }
    }

#pragma unroll
    for (int i = 0; i < 4; i++) {
        float2 f = __half22float2(acc[i]);
        *(float2*)&sS[ws][gi][li * 8 + 2 * i] = f;
    }
    __syncwarp();

    int o0 = 2 * lane;
#pragma unroll
    for (int q = 0; q < 4; q++) {
        int nq = nBase + q;
        if (nq >= nN) break;
        float y0 = 0.f, y1 = 0.f;
#pragma unroll 8
        for (int k = 0; k < 64; k++) {
            float sk = sS[ws][q][k];
            float2 av = __half22float2(*(const __half2*)&sKy[k * 66 + o0]);
            y0 += av.x * sk;
            y1 += av.y * sk;
        }
        size_t off = (size_t)nq * NOPEN + o0;
        float2 xv = *(const float2*)&g_x[off];
        xv.x -= DTH * y0;
        xv.y -= DTH * y1;

        __syncwarp();
        sS[ws][q][o0] = xv.x; sS[ws][q][o0 + 1] = xv.y;
        __syncwarp();
        float v0 = 0.f, v1 = 0.f;
#pragma unroll 8
        for (int k = 0; k < 64; k++) {
            float xk = sS[ws][q][k];
            float2 av = __half22float2(*(const __half2*)&sKp[k * 66 + o0]);
            v0 += av.x * xk;
            v1 += av.y * xk;
        }

        if (!last) {
            *(float2*)&g_x[off] = xv;
            pout[(size_t)nq * 32 + lane] = __floats2half2_rn(v0, v1);
        } else {
            float m = fmaxf(v0, v1);
#pragma unroll
            for (int o = 16; o; o >>= 1)
                m = fmaxf(m, __shfl_xor_sync(0xffffffffu, m, o));
            float s = expf(v0 - m) + expf(v1 - m);
#pragma unroll
            for (int o = 16; o; o >>= 1)
                s += __shfl_xor_sync(0xffffffffu, s, o);
            float lse = m + logf(s);
            float2 r;
            r.x = v0 - lse;
            r.y = v1 - lse;
            *(float2*)&out[(size_t)nq * NOPEN + o0] = r;
        }
    }
}

// ---------------- launch ----------------
extern "C" void kernel_launch(void* const* d_in, const int* in_sizes, int n_in,
                              void* d_out, int out_size) {
    const float* xn   = (const float*)d_in[0];
    const int*   iInd = (const int*)d_in[1];
    const int*   jInd = (const int*)d_in[2];
    int base = 3;
    if (n_in >= 7 && in_sizes[3] == 1) base = 4;
    const float* K1  = (const float*)d_in[base];
    const float* KN1 = (const float*)d_in[base + 1];
    const float* KC  = (const float*)d_in[base + 2];

    int nN = in_sizes[0] / NNIN;
    int nE = in_sizes[1];

    int nodeBlocks8 = (nN + 7) / 8;
    int layerBlocks = (nN + 31) / 32;
    int nb256 = (nN + 255) / 256;
    int eb256 = (nE + 255) / 256;
    int nPad4 = (nN + 3) / 4;
    int scanBlocks = (nPad4 + SCAN_B - 1) / SCAN_B;

    // CSR build + norm
    init_kernel<<<nb256, 256>>>(nN);
    count_kernel<<<eb256, 256>>>(iInd, jInd, nE);
    d2_kernel<<<nb256, 256>>>(nN);
    scanA_kernel<<<scanBlocks, SCAN_B>>>(nPad4);
    scanB_kernel<<<1, 256>>>(scanBlocks);
    scanC_kernel<<<scanBlocks, SCAN_B>>>(nPad4);
    fill_kernel<<<eb256, 256>>>(iInd, jInd, nE);

    // network
    x0_kernel<<<nb256, 256>>>(xn, K1, nN);
    pre_kernel<<<nodeBlocks8, 256>>>(KN1, nN);
    for (int l = 0; l < 4; l++)
        layer_kernel<<<layerBlocks, 256>>>(KN1, KC, (float*)d_out, nN, l & 1,
                                           l == 3 ? 1 : 0);
}